// round 13
// baseline (speedup 1.0000x reference)
#include <cuda_runtime.h>
#include <cuda_fp16.h>
#include <cstdint>
#include <cstddef>

// ----- problem constants -----
#define LSITES  784
#define CHI     128
#define BATCH   1024
#define NCLS    10
#define WROW    264               // padded k-stride of transposed W (halves)
#define SITE_HALVES (CHI * WROW)  // 33792 halves per site
#define SITE_BYTES  (SITE_HALVES * 2)  // 67584 B per site
#define BC      16                // samples per CTA
#define NCTA    (BATCH / BC)      // 64
#define CSZ     8                 // cluster size (W multicast group)
#define HROW    132               // classifier h row stride (floats)
#define AROW    136               // padded A row stride (halves), K=128
#define ABUF_HALVES (BC * AROW)   // 2176 halves
#define ABUF_BYTES  (ABUF_HALVES * 2)   // 4352
#define SMEM_A_OFF   (2 * SITE_BYTES)               // 135168
#define SMEM_MB_OFF  (SMEM_A_OFF + 2 * ABUF_BYTES)  // 143872: full0,full1,empty0,empty1
#define SMEM_TOTAL   (SMEM_MB_OFF + 32)             // 143904

// fp16 transposed weights: Wt[site][b][k], k = s*128 + a, row stride WROW
__device__ __half g_Wt[(size_t)LSITES * SITE_HALVES];   // ~50.5 MB static scratch

// ---------------------------------------------------------------------------
// Prepass: W fp32 [n][s][a][b]  ->  fp16 Wt [n][b][k=s*128+a], padded rows
// ---------------------------------------------------------------------------
__global__ void __launch_bounds__(256) prep_kernel(const float* __restrict__ W) {
    extern __shared__ __half sw[];   // [256][132] halves
    const int n   = blockIdx.x;
    const int tid = threadIdx.x;
    const float* Wg = W + (size_t)n * (2 * CHI * CHI);

    for (int i = 0; i < 128; ++i) {
        int e = i * 256 + tid;
        int k = e >> 7;
        int b = e & 127;
        sw[k * 132 + b] = __float2half_rn(Wg[e]);
    }
    __syncthreads();

    const int w    = tid >> 5;
    const int lane = tid & 31;
    for (int r = 0; r < 16; ++r) {
        int b  = w * 16 + r;
        int k0 = lane * 8;
        __align__(16) __half tmp[8];
#pragma unroll
        for (int j = 0; j < 8; ++j) tmp[j] = sw[(k0 + j) * 132 + b];
        *(uint4*)(&g_Wt[((size_t)n * CHI + b) * WROW + k0]) = *(uint4*)tmp;
    }
}

// ---------------------------------------------------------------------------
__device__ __forceinline__ void mbar_wait(uint32_t mbar, uint32_t parity) {
    asm volatile(
        "{\n\t.reg .pred P;\n"
        "W%=:\n\t"
        "mbarrier.try_wait.parity.acquire.cta.shared::cta.b64 P, [%0], %1, 0x989680;\n\t"
        "@!P bra W%=;\n\t}"
        :: "r"(mbar), "r"(parity) : "memory");
}
__device__ __forceinline__ void mbar_wait_cluster(uint32_t mbar, uint32_t parity) {
    asm volatile(
        "{\n\t.reg .pred P;\n"
        "W%=:\n\t"
        "mbarrier.try_wait.parity.acquire.cluster.shared::cta.b64 P, [%0], %1, 0x989680;\n\t"
        "@!P bra W%=;\n\t}"
        :: "r"(mbar), "r"(parity) : "memory");
}

// ---------------------------------------------------------------------------
// Main kernel: R4 consumer structure + 8-CTA-cluster TMA-multicast W feed.
// Each CTA: own 16-sample slab, full N=128, register-resident h, one
// __syncthreads per site. W staged once per cluster via multicast bulk copy.
// ---------------------------------------------------------------------------
__global__ void __launch_bounds__(256, 1) __cluster_dims__(CSZ, 1, 1)
mps_kernel(const float* __restrict__ x,
           const float* __restrict__ V,
           float* __restrict__ out) {
    extern __shared__ char smem[];
    __half* Wbuf = (__half*)smem;                       // [2][SITE_HALVES]
    __half* Abuf = (__half*)(smem + SMEM_A_OFF);        // [2][BC][AROW] fp16(h)
    const uint32_t mb = (uint32_t)__cvta_generic_to_shared(smem + SMEM_MB_OFF);
    // mb+0, mb+8 : full[0..1]  (count 1, tx)     mb+16, mb+24 : empty[0..1] (count 64)

    const int tid  = threadIdx.x;
    const int cta  = blockIdx.x;
    const int w    = tid >> 5;               // warp 0..7 -> N range [w*16, w*16+16)
    const int lane = tid & 31;
    const int g    = lane >> 2;              // 0..7
    const int tg   = lane & 3;               // 0..3
    const int c0   = w * 16 + 2 * tg;        // owned h/delta column base

    uint32_t rank;
    asm("mov.u32 %0, %%cluster_ctarank;" : "=r"(rank));
    const bool leader = (rank == 0);

    // h register layout (matches acc fragments):
    //  h[0]=H[g][c0]   h[1]=H[g][c0+1]   h[2]=H[g+8][c0]   h[3]=H[g+8][c0+1]
    //  h[4]=H[g][c0+8] h[5]=H[g][c0+9]   h[6]=H[g+8][c0+8] h[7]=H[g+8][c0+9]
    float h[8];
#pragma unroll
    for (int i = 0; i < 8; ++i) h[i] = 1.0f;

    if (tid == 0) {
        asm volatile("mbarrier.init.shared.b64 [%0], 1;"  :: "r"(mb)      : "memory");
        asm volatile("mbarrier.init.shared.b64 [%0], 1;"  :: "r"(mb + 8)  : "memory");
        asm volatile("mbarrier.init.shared.b64 [%0], 64;" :: "r"(mb + 16) : "memory");
        asm volatile("mbarrier.init.shared.b64 [%0], 64;" :: "r"(mb + 24) : "memory");
    }

    // init Abuf[0] = fp16(1)
    {
        const __half2 one2 = __floats2half2_rn(1.f, 1.f);
        *(__half2*)(Abuf + g * AROW + c0)           = one2;
        *(__half2*)(Abuf + g * AROW + c0 + 8)       = one2;
        *(__half2*)(Abuf + (g + 8) * AROW + c0)     = one2;
        *(__half2*)(Abuf + (g + 8) * AROW + c0 + 8) = one2;
    }
    __syncthreads();
    // cluster-wide: all barriers initialized before any multicast / remote arrive
    asm volatile("barrier.cluster.arrive.aligned;" ::: "memory");
    asm volatile("barrier.cluster.wait.aligned;"   ::: "memory");

    const uint32_t wbuf_s = (uint32_t)__cvta_generic_to_shared(Wbuf);
    const uint32_t abuf_s = (uint32_t)__cvta_generic_to_shared(Abuf);

    // leader's empty barriers, addressed from any CTA
    uint32_t leaderE;
    asm("mapa.shared::cluster.u32 %0, %1, %2;" : "=r"(leaderE) : "r"(mb + 16), "r"(0u));

    // prologue: leader multicasts site 0 into buffer 0 of all 8 CTAs
    if (tid == 0) {
        asm volatile("mbarrier.arrive.expect_tx.shared.b64 _, [%0], %1;"
                     :: "r"(mb), "r"((uint32_t)SITE_BYTES) : "memory");
        if (leader) {
            asm volatile(
                "cp.async.bulk.shared::cluster.global.mbarrier::complete_tx::bytes"
                ".multicast::cluster [%0], [%1], %2, [%3], %4;"
                :: "r"(wbuf_s), "l"((const void*)g_Wt),
                   "r"((uint32_t)SITE_BYTES), "r"(mb), "h"((uint16_t)0xFF)
                : "memory");
        }
    }

    // per-thread x streams: samples cta*16+g and cta*16+g+8, features 0/1
    const int sg0 = cta * BC + g;
    const int sg1 = sg0 + 8;
    const float* px00 = x + ((size_t)sg0 * 2 + 0) * LSITES;
    const float* px01 = x + ((size_t)sg0 * 2 + 1) * LSITES;
    const float* px10 = x + ((size_t)sg1 * 2 + 0) * LSITES;
    const float* px11 = x + ((size_t)sg1 * 2 + 1) * LSITES;
    float cx00 = __ldg(px00), cx01 = __ldg(px01);
    float cx10 = __ldg(px10), cx11 = __ldg(px11);

    // ldmatrix lane addresses
    const uint32_t a_base = abuf_s + (uint32_t)((((lane & 15) * AROW) + ((lane >> 4) * 8)) * 2);
    const int grp = lane >> 3;
    const int r8  = lane & 7;
    const int bn  = w * 16 + ((grp & 2) ? 8 : 0) + r8;
    const int bk  = (grp & 1) ? 8 : 0;
    const uint32_t b_base = wbuf_s + (uint32_t)((bn * WROW + bk) * 2);

    uint32_t ph0 = 0, ph1 = 0;          // full-barrier parities
    uint32_t phE0 = 0, phE1 = 0;        // leader empty-barrier parities

    for (int n = 0; n < LSITES; ++n) {
        const int p = n & 1;

        // stage site n+1 into the other buffer: leader multicast, all expect
        if (tid == 0 && n + 1 < LSITES) {
            const uint32_t mnext = mb + (uint32_t)((1 - p) * 8);
            asm volatile("mbarrier.arrive.expect_tx.shared.b64 _, [%0], %1;"
                         :: "r"(mnext), "r"((uint32_t)SITE_BYTES) : "memory");
            if (leader) {
                if (n >= 1) {   // WAR: wait all 64 warp-arrivals from site n-1's readers
                    const uint32_t eb = mb + 16 + (uint32_t)((1 - p) * 8);
                    if (1 - p) { mbar_wait_cluster(eb, phE1); phE1 ^= 1; }
                    else       { mbar_wait_cluster(eb, phE0); phE0 ^= 1; }
                }
                asm volatile(
                    "cp.async.bulk.shared::cluster.global.mbarrier::complete_tx::bytes"
                    ".multicast::cluster [%0], [%1], %2, [%3], %4;"
                    :: "r"(wbuf_s + (uint32_t)((1 - p) * SITE_BYTES)),
                       "l"((const void*)(g_Wt + (size_t)(n + 1) * SITE_HALVES)),
                       "r"((uint32_t)SITE_BYTES), "r"(mnext), "h"((uint16_t)0xFF)
                    : "memory");
            }
        }

        // prefetch x for next site
        float nx00 = 0.f, nx01 = 0.f, nx10 = 0.f, nx11 = 0.f;
        if (n + 1 < LSITES) {
            nx00 = __ldg(px00 + n + 1); nx01 = __ldg(px01 + n + 1);
            nx10 = __ldg(px10 + n + 1); nx11 = __ldg(px11 + n + 1);
        }

        // A fragments: 8 chunks of fp16(h), shared by both GEMMs
        uint32_t a[8][4];
        {
            const uint32_t ab = a_base + (uint32_t)(p * ABUF_BYTES);
#pragma unroll
            for (int ca = 0; ca < 8; ++ca) {
                asm volatile(
                    "ldmatrix.sync.aligned.m8n8.x4.shared.b16 {%0,%1,%2,%3}, [%4];\n"
                    : "=r"(a[ca][0]), "=r"(a[ca][1]), "=r"(a[ca][2]), "=r"(a[ca][3])
                    : "r"(ab + (uint32_t)(ca * 32)));
            }
        }

        // wait for this site's W buffer (multicast completion on local barrier)
        mbar_wait(mb + (uint32_t)(p * 8), p ? ph1 : ph0);
        if (p) ph1 ^= 1; else ph0 ^= 1;

        // two GEMMs (s = k-half), 4 independent acc chains of depth 8
        float acc0[8], acc1[8];
#pragma unroll
        for (int i = 0; i < 8; ++i) { acc0[i] = 0.f; acc1[i] = 0.f; }
        {
            const uint32_t bl = b_base + (uint32_t)(p * SITE_BYTES);
#pragma unroll
            for (int c = 0; c < 16; ++c) {
                const int ca = c & 7;
                float* acc = (c & 8) ? acc1 : acc0;
                uint32_t b0, b1, b2, b3;
                asm volatile(
                    "ldmatrix.sync.aligned.m8n8.x4.shared.b16 {%0,%1,%2,%3}, [%4];\n"
                    : "=r"(b0), "=r"(b1), "=r"(b2), "=r"(b3)
                    : "r"(bl + (uint32_t)(c * 32)));
                asm volatile(
                    "mma.sync.aligned.m16n8k16.row.col.f32.f16.f16.f32 "
                    "{%0,%1,%2,%3}, {%4,%5,%6,%7}, {%8,%9}, {%0,%1,%2,%3};\n"
                    : "+f"(acc[0]), "+f"(acc[1]), "+f"(acc[2]), "+f"(acc[3])
                    : "r"(a[ca][0]), "r"(a[ca][1]), "r"(a[ca][2]), "r"(a[ca][3]),
                      "r"(b0), "r"(b1));
                asm volatile(
                    "mma.sync.aligned.m16n8k16.row.col.f32.f16.f16.f32 "
                    "{%0,%1,%2,%3}, {%4,%5,%6,%7}, {%8,%9}, {%0,%1,%2,%3};\n"
                    : "+f"(acc[4]), "+f"(acc[5]), "+f"(acc[6]), "+f"(acc[7])
                    : "r"(a[ca][0]), "r"(a[ca][1]), "r"(a[ca][2]), "r"(a[ca][3]),
                      "r"(b2), "r"(b3));
            }
        }

        // this warp's B reads for buffer p are done -> release to leader's empty[p]
        // (fire-and-forget; leader waits ~1.5 sites later; skip tail sites no one waits)
        if (lane == 0 && n + 2 < LSITES) {
            asm volatile("mbarrier.arrive.release.cluster.shared::cluster.b64 _, [%0];"
                         :: "r"(leaderE + (uint32_t)(p * 8)) : "memory");
        }

        // fold: h += x0[row]*delta0 + x1[row]*delta1   (f32, register-only)
        h[0] += cx00 * acc0[0] + cx01 * acc1[0];
        h[1] += cx00 * acc0[1] + cx01 * acc1[1];
        h[2] += cx10 * acc0[2] + cx11 * acc1[2];
        h[3] += cx10 * acc0[3] + cx11 * acc1[3];
        h[4] += cx00 * acc0[4] + cx01 * acc1[4];
        h[5] += cx00 * acc0[5] + cx01 * acc1[5];
        h[6] += cx10 * acc0[6] + cx11 * acc1[6];
        h[7] += cx10 * acc0[7] + cx11 * acc1[7];

        // publish fp16(h) into next site's A buffer
        {
            __half* ad = Abuf + (1 - p) * ABUF_HALVES;
            *(__half2*)(ad + g * AROW + c0)           = __floats2half2_rn(h[0], h[1]);
            *(__half2*)(ad + g * AROW + c0 + 8)       = __floats2half2_rn(h[4], h[5]);
            *(__half2*)(ad + (g + 8) * AROW + c0)     = __floats2half2_rn(h[2], h[3]);
            *(__half2*)(ad + (g + 8) * AROW + c0 + 8) = __floats2half2_rn(h[6], h[7]);
        }

        cx00 = nx00; cx01 = nx01; cx10 = nx10; cx11 = nx11;
        __syncthreads();
    }

    // dump h to smem (reuse Wbuf region) for the classifier
    float* Fh = (float*)smem;   // [16][HROW]
    Fh[g * HROW + c0]           = h[0];
    Fh[g * HROW + c0 + 1]       = h[1];
    Fh[g * HROW + c0 + 8]       = h[4];
    Fh[g * HROW + c0 + 9]       = h[5];
    Fh[(g + 8) * HROW + c0]     = h[2];
    Fh[(g + 8) * HROW + c0 + 1] = h[3];
    Fh[(g + 8) * HROW + c0 + 8] = h[6];
    Fh[(g + 8) * HROW + c0 + 9] = h[7];
    __syncthreads();

    // classifier: logits = h @ V  (16 samples x 10 classes per CTA)
    if (tid < BC * NCLS) {
        int r = tid / NCLS, c = tid % NCLS;
        const float* hr = Fh + r * HROW;
        float s = 0.f;
#pragma unroll 8
        for (int a = 0; a < CHI; ++a) s += hr[a] * __ldg(V + a * NCLS + c);
        out[(size_t)(cta * BC + r) * NCLS + c] = s;
    }

    // no CTA exits while peers' remote ops may target this CTA's smem
    asm volatile("barrier.cluster.arrive.aligned;" ::: "memory");
    asm volatile("barrier.cluster.wait.aligned;"   ::: "memory");
}

// ---------------------------------------------------------------------------
extern "C" void kernel_launch(void* const* d_in, const int* in_sizes, int n_in,
                              void* d_out, int out_size) {
    const float* x = nullptr;  // 1024*2*784    = 1605632
    const float* W = nullptr;  // 784*2*128*128 = 25690112
    const float* V = nullptr;  // 128*10        = 1280
    for (int i = 0; i < n_in; ++i) {
        if (in_sizes[i] == BATCH * 2 * LSITES)            x = (const float*)d_in[i];
        else if (in_sizes[i] == LSITES * 2 * CHI * CHI)   W = (const float*)d_in[i];
        else if (in_sizes[i] == CHI * NCLS)               V = (const float*)d_in[i];
    }
    float* out = (float*)d_out;

    static_assert(SMEM_TOTAL == 143904, "smem layout");

    cudaFuncSetAttribute(prep_kernel, cudaFuncAttributeMaxDynamicSharedMemorySize, SITE_BYTES);
    cudaFuncSetAttribute(mps_kernel,  cudaFuncAttributeMaxDynamicSharedMemorySize, SMEM_TOTAL);

    prep_kernel<<<LSITES, 256, SITE_BYTES>>>(W);
    mps_kernel<<<NCTA, 256, SMEM_TOTAL>>>(x, V, out);
    (void)out_size;
}

// round 14
// speedup vs baseline: 1.2645x; 1.2645x over previous
#include <cuda_runtime.h>
#include <cuda_fp16.h>
#include <cstdint>
#include <cstddef>

// ----- problem constants -----
#define LSITES  784
#define CHI     128
#define BATCH   1024
#define NCLS    10
#define WROW    264               // padded k-stride of transposed W (halves)
#define SITE_HALVES (CHI * WROW)  // 33792 halves per site
#define SITE_BYTES  (SITE_HALVES * 2)  // 67584 B per site
#define BC      32                // samples per CTA (2 slabs of 16)
#define SLAB    16
#define NCTA    (BATCH / BC)      // 32
#define THREADS 512
#define HROW    132               // classifier h row stride (floats)
#define AROW    136               // padded A row stride (halves), K=128
#define ABUF_HALVES (SLAB * AROW) // 2176 halves per slab buffer
#define ABUF_BYTES  (ABUF_HALVES * 2)   // 4352
#define SMEM_A_OFF   (2 * SITE_BYTES)               // 135168
#define SMEM_MB_OFF  (SMEM_A_OFF + 4 * ABUF_BYTES)  // 152576  [slab][buf]
#define SMEM_TOTAL   (SMEM_MB_OFF + 16)             // 152592

// fp16 transposed weights: Wt[site][b][k], k = s*128 + a, row stride WROW
__device__ __half g_Wt[(size_t)LSITES * SITE_HALVES];   // ~50.5 MB static scratch

// ---------------------------------------------------------------------------
// Prepass: W fp32 [n][s][a][b]  ->  fp16 Wt [n][b][k=s*128+a], padded rows
// ---------------------------------------------------------------------------
__global__ void __launch_bounds__(256) prep_kernel(const float* __restrict__ W) {
    extern __shared__ __half sw[];   // [256][132] halves
    const int n   = blockIdx.x;
    const int tid = threadIdx.x;
    const float* Wg = W + (size_t)n * (2 * CHI * CHI);

    for (int i = 0; i < 128; ++i) {
        int e = i * 256 + tid;
        int k = e >> 7;
        int b = e & 127;
        sw[k * 132 + b] = __float2half_rn(Wg[e]);
    }
    __syncthreads();

    const int w    = tid >> 5;
    const int lane = tid & 31;
    for (int r = 0; r < 16; ++r) {
        int b  = w * 16 + r;
        int k0 = lane * 8;
        __align__(16) __half tmp[8];
#pragma unroll
        for (int j = 0; j < 8; ++j) tmp[j] = sw[(k0 + j) * 132 + b];
        *(uint4*)(&g_Wt[((size_t)n * CHI + b) * WROW + k0]) = *(uint4*)tmp;
    }
}

// ---------------------------------------------------------------------------
__device__ __forceinline__ void mbar_wait(uint32_t mbar, uint32_t parity) {
    asm volatile(
        "{\n\t.reg .pred P;\n"
        "W%=:\n\t"
        "mbarrier.try_wait.parity.acquire.cta.shared::cta.b64 P, [%0], %1, 0x989680;\n\t"
        "@!P bra W%=;\n\t}"
        :: "r"(mbar), "r"(parity) : "memory");
}

// ---------------------------------------------------------------------------
// Main kernel: 512 threads = two independent 16-sample slab pipelines
// (warps 0-7 slab 0, warps 8-15 slab 1), each identical to the R4 design:
// register-resident h, A = fp16(h) in smem, x folded post-MMA in f32,
// shared W double-buffer via TMA, one __syncthreads per site.
// ---------------------------------------------------------------------------
__global__ void __launch_bounds__(THREADS, 1) mps_kernel(const float* __restrict__ x,
                                                         const float* __restrict__ V,
                                                         float* __restrict__ out) {
    extern __shared__ char smem[];
    __half* Wbuf = (__half*)smem;                       // [2][SITE_HALVES]
    __half* Abuf = (__half*)(smem + SMEM_A_OFF);        // [2 slab][2 buf][ABUF_HALVES]
    const uint32_t mb = (uint32_t)__cvta_generic_to_shared(smem + SMEM_MB_OFF);

    const int tid  = threadIdx.x;
    const int cta  = blockIdx.x;
    const int kg   = tid >> 8;               // slab 0/1 (warps 0-7 / 8-15)
    const int wt   = tid & 255;
    const int w    = wt >> 5;                // warp 0..7 within slab -> cols [w*16,+16)
    const int lane = tid & 31;
    const int g    = lane >> 2;              // 0..7
    const int tg   = lane & 3;               // 0..3
    const int c0   = w * 16 + 2 * tg;        // owned h/delta column base

    // h register layout (matches acc fragments):
    //  h[0]=H[g][c0]   h[1]=H[g][c0+1]   h[2]=H[g+8][c0]   h[3]=H[g+8][c0+1]
    //  h[4]=H[g][c0+8] h[5]=H[g][c0+9]   h[6]=H[g+8][c0+8] h[7]=H[g+8][c0+9]
    float h[8];
#pragma unroll
    for (int i = 0; i < 8; ++i) h[i] = 1.0f;

    if (tid == 0) {
        asm volatile("mbarrier.init.shared.b64 [%0], 1;" :: "r"(mb)     : "memory");
        asm volatile("mbarrier.init.shared.b64 [%0], 1;" :: "r"(mb + 8) : "memory");
    }

    // init this slab's Abuf[buf 0] = fp16(1)
    {
        const __half one = __float2half_rn(1.f);
        __half* a0 = Abuf + kg * 2 * ABUF_HALVES;
        for (int i = wt; i < ABUF_HALVES; i += 256) a0[i] = one;
    }
    __syncthreads();

    const uint32_t wbuf_s = (uint32_t)__cvta_generic_to_shared(Wbuf);
    const uint32_t abuf_s = (uint32_t)__cvta_generic_to_shared(Abuf);

    // prologue: stage site 0 into W buffer 0
    if (tid == 0) {
        asm volatile("mbarrier.arrive.expect_tx.shared.b64 _, [%0], %1;"
                     :: "r"(mb), "r"((uint32_t)SITE_BYTES) : "memory");
        asm volatile(
            "cp.async.bulk.shared::cluster.global.mbarrier::complete_tx::bytes [%0], [%1], %2, [%3];"
            :: "r"(wbuf_s), "l"((const void*)g_Wt), "r"((uint32_t)SITE_BYTES), "r"(mb)
            : "memory");
    }

    // per-thread x streams: samples cta*32 + kg*16 + g (+8), both features
    const int sg0 = cta * BC + kg * SLAB + g;
    const int sg1 = sg0 + 8;
    const float* px00 = x + ((size_t)sg0 * 2 + 0) * LSITES;
    const float* px01 = x + ((size_t)sg0 * 2 + 1) * LSITES;
    const float* px10 = x + ((size_t)sg1 * 2 + 0) * LSITES;
    const float* px11 = x + ((size_t)sg1 * 2 + 1) * LSITES;
    float cx00 = __ldg(px00), cx01 = __ldg(px01);
    float cx10 = __ldg(px10), cx11 = __ldg(px11);

    // ldmatrix lane addresses
    const uint32_t a_base = abuf_s + (uint32_t)(kg * 2 * ABUF_BYTES) +
        (uint32_t)((((lane & 15) * AROW) + ((lane >> 4) * 8)) * 2);
    const int grp = lane >> 3;
    const int r8  = lane & 7;
    const int bn  = w * 16 + ((grp & 2) ? 8 : 0) + r8;
    const int bk  = (grp & 1) ? 8 : 0;
    const uint32_t b_base = wbuf_s + (uint32_t)((bn * WROW + bk) * 2);

    uint32_t ph0 = 0, ph1 = 0;

    for (int n = 0; n < LSITES; ++n) {
        const int p = n & 1;

        // stage site n+1 into the other W buffer
        if (tid == 0 && n + 1 < LSITES) {
            const uint32_t mnext = mb + (uint32_t)((1 - p) * 8);
            asm volatile("mbarrier.arrive.expect_tx.shared.b64 _, [%0], %1;"
                         :: "r"(mnext), "r"((uint32_t)SITE_BYTES) : "memory");
            asm volatile(
                "cp.async.bulk.shared::cluster.global.mbarrier::complete_tx::bytes [%0], [%1], %2, [%3];"
                :: "r"(wbuf_s + (uint32_t)((1 - p) * SITE_BYTES)),
                   "l"((const void*)(g_Wt + (size_t)(n + 1) * SITE_HALVES)),
                   "r"((uint32_t)SITE_BYTES), "r"(mnext)
                : "memory");
        }

        // prefetch x for next site
        float nx00 = 0.f, nx01 = 0.f, nx10 = 0.f, nx11 = 0.f;
        if (n + 1 < LSITES) {
            nx00 = __ldg(px00 + n + 1); nx01 = __ldg(px01 + n + 1);
            nx10 = __ldg(px10 + n + 1); nx11 = __ldg(px11 + n + 1);
        }

        // A fragments: 8 k-chunks of fp16(h) for this slab, shared by both GEMMs
        uint32_t a[8][4];
        {
            const uint32_t ab = a_base + (uint32_t)(p * ABUF_BYTES);
#pragma unroll
            for (int ca = 0; ca < 8; ++ca) {
                asm volatile(
                    "ldmatrix.sync.aligned.m8n8.x4.shared.b16 {%0,%1,%2,%3}, [%4];\n"
                    : "=r"(a[ca][0]), "=r"(a[ca][1]), "=r"(a[ca][2]), "=r"(a[ca][3])
                    : "r"(ab + (uint32_t)(ca * 32)));
            }
        }

        // wait for this site's W buffer
        mbar_wait(mb + (uint32_t)(p * 8), p ? ph1 : ph0);
        if (p) ph1 ^= 1; else ph0 ^= 1;

        // two GEMMs (s = k-half), 4 independent acc chains of depth 8
        float acc0[8], acc1[8];
#pragma unroll
        for (int i = 0; i < 8; ++i) { acc0[i] = 0.f; acc1[i] = 0.f; }
        {
            const uint32_t bl = b_base + (uint32_t)(p * SITE_BYTES);
#pragma unroll
            for (int c = 0; c < 16; ++c) {
                const int ca = c & 7;
                float* acc = (c & 8) ? acc1 : acc0;
                uint32_t b0, b1, b2, b3;
                asm volatile(
                    "ldmatrix.sync.aligned.m8n8.x4.shared.b16 {%0,%1,%2,%3}, [%4];\n"
                    : "=r"(b0), "=r"(b1), "=r"(b2), "=r"(b3)
                    : "r"(bl + (uint32_t)(c * 32)));
                asm volatile(
                    "mma.sync.aligned.m16n8k16.row.col.f32.f16.f16.f32 "
                    "{%0,%1,%2,%3}, {%4,%5,%6,%7}, {%8,%9}, {%0,%1,%2,%3};\n"
                    : "+f"(acc[0]), "+f"(acc[1]), "+f"(acc[2]), "+f"(acc[3])
                    : "r"(a[ca][0]), "r"(a[ca][1]), "r"(a[ca][2]), "r"(a[ca][3]),
                      "r"(b0), "r"(b1));
                asm volatile(
                    "mma.sync.aligned.m16n8k16.row.col.f32.f16.f16.f32 "
                    "{%0,%1,%2,%3}, {%4,%5,%6,%7}, {%8,%9}, {%0,%1,%2,%3};\n"
                    : "+f"(acc[4]), "+f"(acc[5]), "+f"(acc[6]), "+f"(acc[7])
                    : "r"(a[ca][0]), "r"(a[ca][1]), "r"(a[ca][2]), "r"(a[ca][3]),
                      "r"(b2), "r"(b3));
            }
        }

        // fold: h += x0[row]*delta0 + x1[row]*delta1   (f32, register-only)
        h[0] += cx00 * acc0[0] + cx01 * acc1[0];
        h[1] += cx00 * acc0[1] + cx01 * acc1[1];
        h[2] += cx10 * acc0[2] + cx11 * acc1[2];
        h[3] += cx10 * acc0[3] + cx11 * acc1[3];
        h[4] += cx00 * acc0[4] + cx01 * acc1[4];
        h[5] += cx00 * acc0[5] + cx01 * acc1[5];
        h[6] += cx10 * acc0[6] + cx11 * acc1[6];
        h[7] += cx10 * acc0[7] + cx11 * acc1[7];

        // publish fp16(h) into this slab's next A buffer
        {
            __half* ad = Abuf + kg * 2 * ABUF_HALVES + (1 - p) * ABUF_HALVES;
            *(__half2*)(ad + g * AROW + c0)           = __floats2half2_rn(h[0], h[1]);
            *(__half2*)(ad + g * AROW + c0 + 8)       = __floats2half2_rn(h[4], h[5]);
            *(__half2*)(ad + (g + 8) * AROW + c0)     = __floats2half2_rn(h[2], h[3]);
            *(__half2*)(ad + (g + 8) * AROW + c0 + 8) = __floats2half2_rn(h[6], h[7]);
        }

        cx00 = nx00; cx01 = nx01; cx10 = nx10; cx11 = nx11;
        __syncthreads();
    }

    // dump h to smem (reuse Wbuf region) for the classifier
    float* Fh = (float*)smem;   // [32][HROW]
    {
        float* fr = Fh + kg * SLAB * HROW;
        fr[g * HROW + c0]           = h[0];
        fr[g * HROW + c0 + 1]       = h[1];
        fr[g * HROW + c0 + 8]       = h[4];
        fr[g * HROW + c0 + 9]       = h[5];
        fr[(g + 8) * HROW + c0]     = h[2];
        fr[(g + 8) * HROW + c0 + 1] = h[3];
        fr[(g + 8) * HROW + c0 + 8] = h[6];
        fr[(g + 8) * HROW + c0 + 9] = h[7];
    }
    __syncthreads();

    // classifier: logits = h @ V  (32 samples x 10 classes per CTA)
    if (tid < BC * NCLS) {
        int r = tid / NCLS, c = tid % NCLS;
        const float* hr = Fh + r * HROW;
        float s = 0.f;
#pragma unroll 8
        for (int a = 0; a < CHI; ++a) s += hr[a] * __ldg(V + a * NCLS + c);
        out[(size_t)(cta * BC + r) * NCLS + c] = s;
    }
}

// ---------------------------------------------------------------------------
extern "C" void kernel_launch(void* const* d_in, const int* in_sizes, int n_in,
                              void* d_out, int out_size) {
    const float* x = nullptr;  // 1024*2*784    = 1605632
    const float* W = nullptr;  // 784*2*128*128 = 25690112
    const float* V = nullptr;  // 128*10        = 1280
    for (int i = 0; i < n_in; ++i) {
        if (in_sizes[i] == BATCH * 2 * LSITES)            x = (const float*)d_in[i];
        else if (in_sizes[i] == LSITES * 2 * CHI * CHI)   W = (const float*)d_in[i];
        else if (in_sizes[i] == CHI * NCLS)               V = (const float*)d_in[i];
    }
    float* out = (float*)d_out;

    static_assert(SMEM_TOTAL == 152592, "smem layout");

    cudaFuncSetAttribute(prep_kernel, cudaFuncAttributeMaxDynamicSharedMemorySize, SITE_BYTES);
    cudaFuncSetAttribute(mps_kernel,  cudaFuncAttributeMaxDynamicSharedMemorySize, SMEM_TOTAL);

    prep_kernel<<<LSITES, 256, SITE_BYTES>>>(W);
    mps_kernel<<<NCTA, THREADS, SMEM_TOTAL>>>(x, V, out);
    (void)out_size;
}